// round 5
// baseline (speedup 1.0000x reference)
#include <cuda_runtime.h>
#include <math.h>
#include <float.h>

// Problem constants
#define T_TOK 16384         // BSZ * SEQ
#define HID   7168
#define NEXP  256
#define NGRP  8
#define GSZ   32            // experts per group
#define TOPKG 4
#define TOPK  8

// Scratch for logits (allocation-free rule: __device__ global)
__device__ __align__(256) float g_logits[(size_t)T_TOK * NEXP];

// ============================================================================
// GEMM: logits[T, E] = X[T, H] * W[E, H]^T   (fp32, FMA pipe)
// Tile: BM=128 x BN=64, BK=16, 256 threads, 8x4 per-thread micro-tile,
// double-buffered smem, register prefetch, 1 sync per K-step.
// Accuracy: cascade accumulation — 64-term fp32 chunks folded into a
// Kahan-compensated fp32 master. Logit error ~3e-7 (vs ~3e-6 for one long
// sequential fp32 chain), which is what keeps top-k index selection stable
// against the fp32 reference.
// ============================================================================
#define BM 128
#define BN 64
#define BK 16
#define KITERS (HID / BK)   // 448
#define FLUSH_MASK 3        // fold chunk into master every 4 k-tiles (64 terms)

__global__ __launch_bounds__(256, 2)
void gemm_xw_kernel(const float* __restrict__ X, const float* __restrict__ W)
{
    __shared__ __align__(16) float As[2][BK][BM];  // 16 KB
    __shared__ __align__(16) float Bs[2][BK][BN];  //  8 KB

    const int tid = threadIdx.x;
    const int bm  = blockIdx.y;
    const int bn  = blockIdx.x;

    const float* Xb = X + (size_t)bm * BM * HID;
    const float* Wb = W + (size_t)bn * BN * HID;

    // X tile: 128 rows x 16 cols = 512 float4; thread handles f=tid, f=tid+256
    const int xr0 = tid >> 2;
    const int xr1 = (tid + 256) >> 2;
    const int xc  = (tid & 3) * 4;
    // W tile: 64 rows x 16 cols = 256 float4
    const int wr = tid >> 2;
    const int wc = (tid & 3) * 4;

    const int ty = tid >> 4;   // 0..15 -> rows ty*8 .. ty*8+7
    const int tx = tid & 15;   // 0..15 -> cols tx*4 .. tx*4+3

    float4 xa, xbv, wv;

    // load tile 0 directly into smem buffer 0
    xa  = *(const float4*)(Xb + (size_t)xr0 * HID + xc);
    xbv = *(const float4*)(Xb + (size_t)xr1 * HID + xc);
    wv  = *(const float4*)(Wb + (size_t)wr  * HID + wc);
    As[0][xc+0][xr0] = xa.x;  As[0][xc+1][xr0] = xa.y;
    As[0][xc+2][xr0] = xa.z;  As[0][xc+3][xr0] = xa.w;
    As[0][xc+0][xr1] = xbv.x; As[0][xc+1][xr1] = xbv.y;
    As[0][xc+2][xr1] = xbv.z; As[0][xc+3][xr1] = xbv.w;
    Bs[0][wc+0][wr]  = wv.x;  Bs[0][wc+1][wr]  = wv.y;
    Bs[0][wc+2][wr]  = wv.z;  Bs[0][wc+3][wr]  = wv.w;
    __syncthreads();

    float accf[8][4];    // current chunk (<= 64 products)
    float master[8][4];  // Kahan master sum
    float comp[8][4];    // Kahan compensation
    #pragma unroll
    for (int i = 0; i < 8; ++i)
        #pragma unroll
        for (int j = 0; j < 4; ++j) {
            accf[i][j] = 0.0f; master[i][j] = 0.0f; comp[i][j] = 0.0f;
        }

    for (int kt = 0; kt < KITERS; ++kt) {
        const int buf  = kt & 1;
        const bool more = (kt + 1 < KITERS);

        // issue global prefetch for next tile (overlaps with compute below)
        if (more) {
            const int k0 = (kt + 1) * BK;
            xa  = *(const float4*)(Xb + (size_t)xr0 * HID + k0 + xc);
            xbv = *(const float4*)(Xb + (size_t)xr1 * HID + k0 + xc);
            wv  = *(const float4*)(Wb + (size_t)wr  * HID + k0 + wc);
        }

        // compute current tile from smem[buf]
        #pragma unroll
        for (int k = 0; k < BK; ++k) {
            const float4 a0 = *(const float4*)(&As[buf][k][ty * 8]);
            const float4 a1 = *(const float4*)(&As[buf][k][ty * 8 + 4]);
            const float4 b4 = *(const float4*)(&Bs[buf][k][tx * 4]);
            const float am[8] = {a0.x, a0.y, a0.z, a0.w, a1.x, a1.y, a1.z, a1.w};
            const float bb[4] = {b4.x, b4.y, b4.z, b4.w};
            #pragma unroll
            for (int i = 0; i < 8; ++i)
                #pragma unroll
                for (int j = 0; j < 4; ++j)
                    accf[i][j] = fmaf(am[i], bb[j], accf[i][j]);
        }

        // fold chunk into Kahan master every 4 tiles (64 terms)
        if ((kt & FLUSH_MASK) == FLUSH_MASK) {
            #pragma unroll
            for (int i = 0; i < 8; ++i)
                #pragma unroll
                for (int j = 0; j < 4; ++j) {
                    const float y = __fsub_rn(accf[i][j], comp[i][j]);
                    const float t = __fadd_rn(master[i][j], y);
                    comp[i][j]   = __fsub_rn(__fsub_rn(t, master[i][j]), y);
                    master[i][j] = t;
                    accf[i][j]   = 0.0f;
                }
        }

        // store prefetched regs into the other buffer
        if (more) {
            const int nb = buf ^ 1;
            As[nb][xc+0][xr0] = xa.x;  As[nb][xc+1][xr0] = xa.y;
            As[nb][xc+2][xr0] = xa.z;  As[nb][xc+3][xr0] = xa.w;
            As[nb][xc+0][xr1] = xbv.x; As[nb][xc+1][xr1] = xbv.y;
            As[nb][xc+2][xr1] = xbv.z; As[nb][xc+3][xr1] = xbv.w;
            Bs[nb][wc+0][wr]  = wv.x;  Bs[nb][wc+1][wr]  = wv.y;
            Bs[nb][wc+2][wr]  = wv.z;  Bs[nb][wc+3][wr]  = wv.w;
        }
        __syncthreads();
    }

    // epilogue: write logits (448 % 4 == 0, so last chunk already folded)
    float* Cb = g_logits + (size_t)(bm * BM) * NEXP + bn * BN;
    #pragma unroll
    for (int i = 0; i < 8; ++i) {
        float4 v = make_float4(master[i][0], master[i][1],
                               master[i][2], master[i][3]);
        *(float4*)(Cb + (size_t)(ty * 8 + i) * NEXP + tx * 4) = v;
    }
}

// ============================================================================
// Routing: one warp per token.
// slot j (0..7) on lane l holds expert e = j*32 + l  ->  slot j == group j.
// ============================================================================
__global__ __launch_bounds__(256)
void topk_kernel(const float* __restrict__ bias, float* __restrict__ out)
{
    const int gwarp = (blockIdx.x * blockDim.x + threadIdx.x) >> 5;
    const int lane  = threadIdx.x & 31;
    if (gwarp >= T_TOK) return;
    const int t = gwarp;

    const float* lg = g_logits + (size_t)t * NEXP;

    float s[8], c[8];
    #pragma unroll
    for (int j = 0; j < 8; ++j) {
        const float v = lg[j * GSZ + lane];
        // sigmoid in fp64, rounded to fp32: immune to --use_fast_math expf
        // approximation; matches the reference's fp32 score to ~1 ulp.
        const float sig = (float)(1.0 / (1.0 + exp(-(double)v)));
        s[j] = sig;
        c[j] = __fadd_rn(sig, bias[j * GSZ + lane]);
    }

    // group score = sum of top-2 corrected scores within each group (warp dim)
    float gs[8];
    #pragma unroll
    for (int j = 0; j < 8; ++j) {
        float v = c[j]; int li = lane;
        #pragma unroll
        for (int off = 16; off; off >>= 1) {
            const float ov = __shfl_xor_sync(0xffffffffu, v, off);
            const int   ol = __shfl_xor_sync(0xffffffffu, li, off);
            if (ov > v || (ov == v && ol < li)) { v = ov; li = ol; }
        }
        float v2 = (lane == li) ? -INFINITY : c[j];   // remove one max instance
        #pragma unroll
        for (int off = 16; off; off >>= 1)
            v2 = fmaxf(v2, __shfl_xor_sync(0xffffffffu, v2, off));
        gs[j] = __fadd_rn(v, v2);
    }

    // top-4 groups (serial, identical on every lane; tie -> lower group index)
    unsigned sel = 0;
    {
        float g2[8];
        #pragma unroll
        for (int j = 0; j < 8; ++j) g2[j] = gs[j];
        #pragma unroll
        for (int r = 0; r < TOPKG; ++r) {
            float best = -INFINITY; int bi = 0;
            #pragma unroll
            for (int j = 0; j < 8; ++j)
                if (g2[j] > best) { best = g2[j]; bi = j; }
            sel |= (1u << bi);
            #pragma unroll
            for (int j = 0; j < 8; ++j) if (j == bi) g2[j] = -INFINITY;
        }
    }

    float candv[8];
    #pragma unroll
    for (int j = 0; j < 8; ++j)
        candv[j] = ((sel >> j) & 1u) ? c[j] : -INFINITY;

    // iterative top-8 over masked corrected scores; tie -> lower expert index
    float wsel[8]; int isel[8];
    #pragma unroll
    for (int r = 0; r < TOPK; ++r) {
        float bv = -INFINITY; int bidx = 0x7fffffff; float bs = 0.0f;
        #pragma unroll
        for (int j = 0; j < 8; ++j) {
            const int ei = j * GSZ + lane;
            if (candv[j] > bv || (candv[j] == bv && ei < bidx)) {
                bv = candv[j]; bidx = ei; bs = s[j];
            }
        }
        #pragma unroll
        for (int off = 16; off; off >>= 1) {
            const float ov = __shfl_xor_sync(0xffffffffu, bv, off);
            const int   oi = __shfl_xor_sync(0xffffffffu, bidx, off);
            const float os = __shfl_xor_sync(0xffffffffu, bs, off);
            if (ov > bv || (ov == bv && oi < bidx)) { bv = ov; bidx = oi; bs = os; }
        }
        isel[r] = bidx;
        wsel[r] = bs;               // weight from UNcorrected sigmoid score
        if (lane == (bidx & 31)) {
            const int slot = bidx >> 5;
            #pragma unroll
            for (int j = 0; j < 8; ++j) if (j == slot) candv[j] = -INFINITY;
        }
    }

    if (lane == 0) {
        float sum = 0.0f;
        #pragma unroll
        for (int r = 0; r < TOPK; ++r) sum = __fadd_rn(sum, wsel[r]);
        const float denom = __fadd_rn(sum, 1e-20f);
        #pragma unroll
        for (int r = 0; r < TOPK; ++r) {
            out[(size_t)t * TOPK + r] = (float)isel[r];                 // topk_idx
            out[(size_t)T_TOK * TOPK + (size_t)t * TOPK + r] =
                (wsel[r] / denom) * 2.5f;                               // topk_weight
        }
    }
}

// ============================================================================
extern "C" void kernel_launch(void* const* d_in, const int* in_sizes, int n_in,
                              void* d_out, int out_size)
{
    // resolve inputs by element count (robust to ordering)
    const float* X = nullptr;  // [T, H]
    const float* W = nullptr;  // [E, H]
    const float* B = nullptr;  // [E]
    for (int i = 0; i < n_in; ++i) {
        if (in_sizes[i] == T_TOK * HID)      X = (const float*)d_in[i];
        else if (in_sizes[i] == NEXP * HID)  W = (const float*)d_in[i];
        else if (in_sizes[i] == NEXP)        B = (const float*)d_in[i];
    }
    float* out = (float*)d_out;

    dim3 grid(NEXP / BN, T_TOK / BM);   // (4, 128) = 512 CTAs
    gemm_xw_kernel<<<grid, 256>>>(X, W);

    // 8 warps per block -> 8 tokens per block
    topk_kernel<<<T_TOK / 8, 256>>>(B, out);
}

// round 7
// speedup vs baseline: 2.3208x; 2.3208x over previous
#include <cuda_runtime.h>
#include <cuda_fp16.h>
#include <math.h>
#include <float.h>
#include <stdint.h>

// Problem constants
#define T_TOK 16384
#define HID   7168
#define NEXP  256
#define NGRP  8
#define GSZ   32
#define TOPKG 4
#define TOPK  8

// GEMM tiling
#define BM 128
#define BN 64
#define BK 32
#define CHUNKS (HID / BK)       // 224

// fp16 split scaling (powers of 2, exactly undone in epilogue).
// X*2^11: lo-half ~1.0 (normal range). W*2^17: lo-half ~0.4 (normal range).
#define XS 2048.0f
#define WS 131072.0f
#define INV_SCALE (1.0 / 268435456.0)   // 2^-28

// SMEM layout: padded row stride 80 bytes (40 halves) -> conflict-free LDS.
// Per stage: A0[10240] A1[10240] B0[5120] B1[5120] = 30720 bytes. 2 stages.
#define A0_OFF 0
#define A1_OFF 10240
#define B0_OFF 20480
#define B1_OFF 25600
#define STAGE_BYTES 30720
#define GEMM_SMEM (2 * STAGE_BYTES)
#define ROWB 80

// Scratch for logits
__device__ __align__(256) float g_logits[(size_t)T_TOK * NEXP];

// ---------------------------------------------------------------------------
// m16n8k16 fp16->fp32 mma (base sm_80+ instruction, valid on compute_100)
// ---------------------------------------------------------------------------
__device__ __forceinline__ void mma16816(float* d, const uint32_t* a,
                                         const uint32_t* b) {
    asm volatile(
        "mma.sync.aligned.m16n8k16.row.col.f32.f16.f16.f32 "
        "{%0,%1,%2,%3}, {%4,%5,%6,%7}, {%8,%9}, {%0,%1,%2,%3};\n"
        : "+f"(d[0]), "+f"(d[1]), "+f"(d[2]), "+f"(d[3])
        : "r"(a[0]), "r"(a[1]), "r"(a[2]), "r"(a[3]), "r"(b[0]), "r"(b[1]));
}

// split scaled fp32x4 into hi/lo fp16 pairs (x - rn16(x) exact via Sterbenz)
__device__ __forceinline__ void split2(float4 v, float scale,
                                       uint2& hi, uint2& lo) {
    const float a = v.x * scale, b = v.y * scale;
    const float c = v.z * scale, d = v.w * scale;
    const __half2 h01 = __floats2half2_rn(a, b);
    const __half2 h23 = __floats2half2_rn(c, d);
    const __half2 l01 = __floats2half2_rn(a - __low2float(h01),
                                          b - __high2float(h01));
    const __half2 l23 = __floats2half2_rn(c - __low2float(h23),
                                          d - __high2float(h23));
    hi.x = *reinterpret_cast<const uint32_t*>(&h01);
    hi.y = *reinterpret_cast<const uint32_t*>(&h23);
    lo.x = *reinterpret_cast<const uint32_t*>(&l01);
    lo.y = *reinterpret_cast<const uint32_t*>(&l23);
}

// ============================================================================
// GEMM: g_logits[T, E] = X * W^T via fp16 2-split on tensor cores (mma.sync).
// 3 products: x0w0 (chunked fp32 acc + Kahan fp32 master, folded every K=128)
//             x0w1 + x1w0 (plain fp32 acc; rounding scaled by 2^-11)
// ============================================================================
__global__ __launch_bounds__(256, 1)
void gemm_mma_kernel(const float* __restrict__ X, const float* __restrict__ W)
{
    extern __shared__ __align__(16) char sm[];
    const int tid  = threadIdx.x;
    const int wid  = tid >> 5;
    const int lane = tid & 31;
    const int g    = lane >> 2;        // mma group id (0..7)
    const int tig  = lane & 3;         // thread in group
    const int wm   = wid & 3;          // warp row (4 x 32 = 128)
    const int wn   = wid >> 2;         // warp col (2 x 32 = 64)
    const int bn   = blockIdx.x;       // 0..3
    const int bm   = blockIdx.y;       // 0..127

    const float* Xb = X + (size_t)bm * BM * HID;
    const float* Wb = W + (size_t)bn * BN * HID;

    // loader mapping: float4 id = tid + p*256; row = (id>>3), f4 = tid&7
    const int lr = tid >> 3;           // 0..31
    const int lf = tid & 7;            // 0..7 (covers 32 floats)

    // ---- load chunk 0 into stage 0 ----
    {
        #pragma unroll
        for (int p = 0; p < 4; ++p) {
            const int row = lr + 32 * p;
            const float4 v = *(const float4*)(Xb + (size_t)row * HID + lf * 4);
            uint2 h, l; split2(v, XS, h, l);
            const uint32_t off = (uint32_t)(row * ROWB + lf * 8);
            *(uint2*)(sm + A0_OFF + off) = h;
            *(uint2*)(sm + A1_OFF + off) = l;
        }
        #pragma unroll
        for (int p = 0; p < 2; ++p) {
            const int row = lr + 32 * p;
            const float4 v = *(const float4*)(Wb + (size_t)row * HID + lf * 4);
            uint2 h, l; split2(v, WS, h, l);
            const uint32_t off = (uint32_t)(row * ROWB + lf * 8);
            *(uint2*)(sm + B0_OFF + off) = h;
            *(uint2*)(sm + B1_OFF + off) = l;
        }
    }
    __syncthreads();

    float acc_hi[2][4][4], acc_ms[2][4][4];
    float master[2][4][4], comp[2][4][4];
    #pragma unroll
    for (int mt = 0; mt < 2; ++mt)
        #pragma unroll
        for (int nt = 0; nt < 4; ++nt)
            #pragma unroll
            for (int e = 0; e < 4; ++e) {
                acc_hi[mt][nt][e] = 0.0f; acc_ms[mt][nt][e] = 0.0f;
                master[mt][nt][e] = 0.0f; comp[mt][nt][e]   = 0.0f;
            }

    // hoisted fragment base offsets (within a stage)
    const uint32_t aRow0 = (uint32_t)((wm * 32 + g) * ROWB);
    const uint32_t bRow0 = (uint32_t)((wn * 32 + g) * ROWB);

    float4 pa[4], pb[2];

    for (int kt = 0; kt < CHUNKS; ++kt) {
        const int buf = kt & 1;
        const uint32_t stage = (uint32_t)buf * STAGE_BYTES;
        const bool more = (kt + 1 < CHUNKS);

        // global prefetch of next chunk into registers
        if (more) {
            const int k0 = (kt + 1) * BK;
            #pragma unroll
            for (int p = 0; p < 4; ++p)
                pa[p] = *(const float4*)(Xb + (size_t)(lr + 32 * p) * HID + k0 + lf * 4);
            #pragma unroll
            for (int p = 0; p < 2; ++p)
                pb[p] = *(const float4*)(Wb + (size_t)(lr + 32 * p) * HID + k0 + lf * 4);
        }

        // compute: 2 k-steps of K=16
        #pragma unroll
        for (int ks = 0; ks < 2; ++ks) {
            const uint32_t ka = (uint32_t)(ks * 32 + tig * 4);
            uint32_t a0[2][4], a1[2][4], b0[4][2], b1[4][2];
            #pragma unroll
            for (int mt = 0; mt < 2; ++mt) {
                const uint32_t r0 = stage + aRow0 + (uint32_t)(mt * 16 * ROWB) + ka;
                const uint32_t r8 = r0 + 8 * ROWB;
                a0[mt][0] = *(const uint32_t*)(sm + A0_OFF + r0);
                a0[mt][1] = *(const uint32_t*)(sm + A0_OFF + r8);
                a0[mt][2] = *(const uint32_t*)(sm + A0_OFF + r0 + 16);
                a0[mt][3] = *(const uint32_t*)(sm + A0_OFF + r8 + 16);
                a1[mt][0] = *(const uint32_t*)(sm + A1_OFF + r0);
                a1[mt][1] = *(const uint32_t*)(sm + A1_OFF + r8);
                a1[mt][2] = *(const uint32_t*)(sm + A1_OFF + r0 + 16);
                a1[mt][3] = *(const uint32_t*)(sm + A1_OFF + r8 + 16);
            }
            #pragma unroll
            for (int nt = 0; nt < 4; ++nt) {
                const uint32_t rb = stage + bRow0 + (uint32_t)(nt * 8 * ROWB) + ka;
                b0[nt][0] = *(const uint32_t*)(sm + B0_OFF + rb);
                b0[nt][1] = *(const uint32_t*)(sm + B0_OFF + rb + 16);
                b1[nt][0] = *(const uint32_t*)(sm + B1_OFF + rb);
                b1[nt][1] = *(const uint32_t*)(sm + B1_OFF + rb + 16);
            }
            #pragma unroll
            for (int mt = 0; mt < 2; ++mt)
                #pragma unroll
                for (int nt = 0; nt < 4; ++nt) {
                    mma16816(acc_hi[mt][nt], a0[mt], b0[nt]);
                    mma16816(acc_ms[mt][nt], a0[mt], b1[nt]);
                    mma16816(acc_ms[mt][nt], a1[mt], b0[nt]);
                }
        }

        // fold hi-chunk into Kahan master every 4 chunks (K=128)
        if ((kt & 3) == 3) {
            #pragma unroll
            for (int mt = 0; mt < 2; ++mt)
                #pragma unroll
                for (int nt = 0; nt < 4; ++nt)
                    #pragma unroll
                    for (int e = 0; e < 4; ++e) {
                        const float y = __fsub_rn(acc_hi[mt][nt][e], comp[mt][nt][e]);
                        const float t = __fadd_rn(master[mt][nt][e], y);
                        comp[mt][nt][e]   = __fsub_rn(__fsub_rn(t, master[mt][nt][e]), y);
                        master[mt][nt][e] = t;
                        acc_hi[mt][nt][e] = 0.0f;
                    }
        }

        // split + store prefetched chunk into the other stage
        if (more) {
            const uint32_t nst = (uint32_t)(buf ^ 1) * STAGE_BYTES;
            #pragma unroll
            for (int p = 0; p < 4; ++p) {
                uint2 h, l; split2(pa[p], XS, h, l);
                const uint32_t off = nst + (uint32_t)((lr + 32 * p) * ROWB + lf * 8);
                *(uint2*)(sm + A0_OFF + off) = h;
                *(uint2*)(sm + A1_OFF + off) = l;
            }
            #pragma unroll
            for (int p = 0; p < 2; ++p) {
                uint2 h, l; split2(pb[p], WS, h, l);
                const uint32_t off = nst + (uint32_t)((lr + 32 * p) * ROWB + lf * 8);
                *(uint2*)(sm + B0_OFF + off) = h;
                *(uint2*)(sm + B1_OFF + off) = l;
            }
        }
        __syncthreads();
    }

    // epilogue: combine in fp64, descale exactly, store fp32 logits
    #pragma unroll
    for (int mt = 0; mt < 2; ++mt)
        #pragma unroll
        for (int nt = 0; nt < 4; ++nt) {
            const int col = bn * BN + wn * 32 + nt * 8 + tig * 2;
            #pragma unroll
            for (int h2 = 0; h2 < 2; ++h2) {
                const int row = bm * BM + wm * 32 + mt * 16 + g + h2 * 8;
                const int e0 = h2 * 2;
                const double v0 = ((double)master[mt][nt][e0]
                                 - (double)comp[mt][nt][e0]
                                 + (double)acc_ms[mt][nt][e0]) * INV_SCALE;
                const double v1 = ((double)master[mt][nt][e0 + 1]
                                 - (double)comp[mt][nt][e0 + 1]
                                 + (double)acc_ms[mt][nt][e0 + 1]) * INV_SCALE;
                float2 o; o.x = (float)v0; o.y = (float)v1;
                *(float2*)(g_logits + (size_t)row * NEXP + col) = o;
            }
        }
}

// ============================================================================
// Routing: one warp per token (unchanged — known exact from round 5).
// ============================================================================
__global__ __launch_bounds__(256)
void topk_kernel(const float* __restrict__ bias, float* __restrict__ out)
{
    const int gwarp = (blockIdx.x * blockDim.x + threadIdx.x) >> 5;
    const int lane  = threadIdx.x & 31;
    if (gwarp >= T_TOK) return;
    const int t = gwarp;

    const float* lg = g_logits + (size_t)t * NEXP;

    float s[8], c[8];
    #pragma unroll
    for (int j = 0; j < 8; ++j) {
        const float v = lg[j * GSZ + lane];
        const float sig = (float)(1.0 / (1.0 + exp(-(double)v)));
        s[j] = sig;
        c[j] = __fadd_rn(sig, bias[j * GSZ + lane]);
    }

    float gs[8];
    #pragma unroll
    for (int j = 0; j < 8; ++j) {
        float v = c[j]; int li = lane;
        #pragma unroll
        for (int off = 16; off; off >>= 1) {
            const float ov = __shfl_xor_sync(0xffffffffu, v, off);
            const int   ol = __shfl_xor_sync(0xffffffffu, li, off);
            if (ov > v || (ov == v && ol < li)) { v = ov; li = ol; }
        }
        float v2 = (lane == li) ? -INFINITY : c[j];
        #pragma unroll
        for (int off = 16; off; off >>= 1)
            v2 = fmaxf(v2, __shfl_xor_sync(0xffffffffu, v2, off));
        gs[j] = __fadd_rn(v, v2);
    }

    unsigned sel = 0;
    {
        float g2[8];
        #pragma unroll
        for (int j = 0; j < 8; ++j) g2[j] = gs[j];
        #pragma unroll
        for (int r = 0; r < TOPKG; ++r) {
            float best = -INFINITY; int bi = 0;
            #pragma unroll
            for (int j = 0; j < 8; ++j)
                if (g2[j] > best) { best = g2[j]; bi = j; }
            sel |= (1u << bi);
            #pragma unroll
            for (int j = 0; j < 8; ++j) if (j == bi) g2[j] = -INFINITY;
        }
    }

    float candv[8];
    #pragma unroll
    for (int j = 0; j < 8; ++j)
        candv[j] = ((sel >> j) & 1u) ? c[j] : -INFINITY;

    float wsel[8]; int isel[8];
    #pragma unroll
    for (int r = 0; r < TOPK; ++r) {
        float bv = -INFINITY; int bidx = 0x7fffffff; float bs = 0.0f;
        #pragma unroll
        for (int j = 0; j < 8; ++j) {
            const int ei = j * GSZ + lane;
            if (candv[j] > bv || (candv[j] == bv && ei < bidx)) {
                bv = candv[j]; bidx = ei; bs = s[j];
            }
        }
        #pragma unroll
        for (int off = 16; off; off >>= 1) {
            const float ov = __shfl_xor_sync(0xffffffffu, bv, off);
            const int   oi = __shfl_xor_sync(0xffffffffu, bidx, off);
            const float os = __shfl_xor_sync(0xffffffffu, bs, off);
            if (ov > bv || (ov == bv && oi < bidx)) { bv = ov; bidx = oi; bs = os; }
        }
        isel[r] = bidx;
        wsel[r] = bs;
        if (lane == (bidx & 31)) {
            const int slot = bidx >> 5;
            #pragma unroll
            for (int j = 0; j < 8; ++j) if (j == slot) candv[j] = -INFINITY;
        }
    }

    if (lane == 0) {
        float sum = 0.0f;
        #pragma unroll
        for (int r = 0; r < TOPK; ++r) sum = __fadd_rn(sum, wsel[r]);
        const float denom = __fadd_rn(sum, 1e-20f);
        #pragma unroll
        for (int r = 0; r < TOPK; ++r) {
            out[(size_t)t * TOPK + r] = (float)isel[r];
            out[(size_t)T_TOK * TOPK + (size_t)t * TOPK + r] =
                (wsel[r] / denom) * 2.5f;
        }
    }
}

// ============================================================================
extern "C" void kernel_launch(void* const* d_in, const int* in_sizes, int n_in,
                              void* d_out, int out_size)
{
    const float* X = nullptr;
    const float* W = nullptr;
    const float* B = nullptr;
    for (int i = 0; i < n_in; ++i) {
        if (in_sizes[i] == T_TOK * HID)      X = (const float*)d_in[i];
        else if (in_sizes[i] == NEXP * HID)  W = (const float*)d_in[i];
        else if (in_sizes[i] == NEXP)        B = (const float*)d_in[i];
    }
    float* out = (float*)d_out;

    cudaFuncSetAttribute(gemm_mma_kernel,
                         cudaFuncAttributeMaxDynamicSharedMemorySize, GEMM_SMEM);

    dim3 grid(NEXP / BN, T_TOK / BM);   // (4, 128) = 512 CTAs
    gemm_mma_kernel<<<grid, 256, GEMM_SMEM>>>(X, W);

    topk_kernel<<<T_TOK / 8, 256>>>(B, out);
}